// round 1
// baseline (speedup 1.0000x reference)
#include <cuda_runtime.h>

// Regional Interaction Module — fully fused per-pixel kernel.
// B=32, C=3, H=W=512. All 1x1 convs algebraically folded into per-pixel
// closed form with composite weight matrices precomputed per thread.
//
// f_f[c] = s1*A[c] + s4*B[c] + v_r*(s2*Sa[c] + s3*Sb[c]) + fu_b[c]
//   A[c] = (fuA . vi_w)[c] . x + (fuA . vi_b)[c]     (x = img rgb)
//   B[c] = (fuB . vi_w)[c] . x + (fuB . vi_b)[c]
//   Sa[c] = sum_j fuA[c][j],  Sb[c] = sum_j fuB[c][j]
//   s1 = sig(q_i*k_i), s2 = sig(q_i*k_r), s3 = sig(q_r*k_r), s4 = sig(q_r*k_i)

#define HW       (512 * 512)
#define PLANE4   (HW / 4)          // 65536 float4 per plane
#define ITERS    4
#define THREADS  256

__device__ __forceinline__ float fast_sigmoid(float x) {
    // 1 / (1 + exp(-x)); __expf = MUFU.EX2 path, __fdividef = MUFU.RCP path.
    return __fdividef(1.0f, 1.0f + __expf(-x));
}

__global__ void __launch_bounds__(THREADS)
rim_kernel(const float* __restrict__ img, const float* __restrict__ mask,
           const float* __restrict__ qi_w, const float* __restrict__ qi_b,
           const float* __restrict__ ki_w, const float* __restrict__ ki_b,
           const float* __restrict__ vi_w, const float* __restrict__ vi_b,
           const float* __restrict__ qr_w, const float* __restrict__ qr_b,
           const float* __restrict__ kr_w, const float* __restrict__ kr_b,
           const float* __restrict__ vr_w, const float* __restrict__ vr_b,
           const float* __restrict__ fu_w, const float* __restrict__ fu_b,
           float* __restrict__ out, int n_q)
{
    // ---- per-thread coefficient setup (L1-broadcast loads, amortized over 16 px) ----
    const float qiw0 = qi_w[0], qiw1 = qi_w[1], qiw2 = qi_w[2], qib = qi_b[0];
    const float kiw0 = ki_w[0], kiw1 = ki_w[1], kiw2 = ki_w[2], kib = ki_b[0];
    const float qrw = qr_w[0], qrb = qr_b[0];
    const float krw = kr_w[0], krb = kr_b[0];
    const float vrw = vr_w[0], vrb = vr_b[0];

    float viw[9], vib[3];
    #pragma unroll
    for (int i = 0; i < 9; i++) viw[i] = vi_w[i];
    #pragma unroll
    for (int i = 0; i < 3; i++) vib[i] = vi_b[i];

    float WA[3][3], WB[3][3], bA[3], bB[3], Sa[3], Sb[3], fub[3];
    #pragma unroll
    for (int c = 0; c < 3; c++) {
        const float a0 = fu_w[c * 6 + 0], a1 = fu_w[c * 6 + 1], a2 = fu_w[c * 6 + 2];
        const float b0 = fu_w[c * 6 + 3], b1 = fu_w[c * 6 + 4], b2 = fu_w[c * 6 + 5];
        Sa[c] = a0 + a1 + a2;
        Sb[c] = b0 + b1 + b2;
        #pragma unroll
        for (int i = 0; i < 3; i++) {
            WA[c][i] = a0 * viw[0 * 3 + i] + a1 * viw[1 * 3 + i] + a2 * viw[2 * 3 + i];
            WB[c][i] = b0 * viw[0 * 3 + i] + b1 * viw[1 * 3 + i] + b2 * viw[2 * 3 + i];
        }
        bA[c]  = a0 * vib[0] + a1 * vib[1] + a2 * vib[2];
        bB[c]  = b0 * vib[0] + b1 * vib[1] + b2 * vib[2];
        fub[c] = fu_b[c];
    }

    auto pixel = [&](float r, float g, float bl, float m,
                     float& o0, float& o1, float& o2) {
        const float qi = fmaf(qiw2, bl, fmaf(qiw1, g, fmaf(qiw0, r, qib)));
        const float ki = fmaf(kiw2, bl, fmaf(kiw1, g, fmaf(kiw0, r, kib)));
        const float qr = fmaf(qrw, m, qrb);
        const float kr = fmaf(krw, m, krb);
        const float vr = fmaf(vrw, m, vrb);
        const float s1 = fast_sigmoid(qi * ki);
        const float s2 = fast_sigmoid(qi * kr);
        const float s3 = fast_sigmoid(qr * kr);
        const float s4 = fast_sigmoid(qr * ki);
        float o[3];
        #pragma unroll
        for (int c = 0; c < 3; c++) {
            const float A  = fmaf(WA[c][2], bl, fmaf(WA[c][1], g, fmaf(WA[c][0], r, bA[c])));
            const float Bv = fmaf(WB[c][2], bl, fmaf(WB[c][1], g, fmaf(WB[c][0], r, bB[c])));
            const float u  = fmaf(s2, Sa[c], s3 * Sb[c]);
            float f = fmaf(s1, A, fub[c]);
            f = fmaf(s4, Bv, f);
            f = fmaf(vr, u, f);
            o[c] = f;
        }
        o0 = o[0]; o1 = o[1]; o2 = o[2];
    };

    const float4* img4  = reinterpret_cast<const float4*>(img);
    const float4* mask4 = reinterpret_cast<const float4*>(mask);
    float4*       out4  = reinterpret_cast<float4*>(out);

    const int tid    = blockIdx.x * blockDim.x + threadIdx.x;
    const int stride = gridDim.x * blockDim.x;

    #pragma unroll
    for (int k = 0; k < ITERS; k++) {
        const int q = tid + k * stride;
        if (q >= n_q) break;
        const int b    = q >> 16;          // q / PLANE4 (PLANE4 = 65536)
        const int sq   = q & (PLANE4 - 1);
        const int base = b * (3 * PLANE4) + sq;   // rgb plane base for this batch

        const float4 R  = img4[base];
        const float4 G  = img4[base + PLANE4];
        const float4 Bc = img4[base + 2 * PLANE4];
        const float4 M  = mask4[q];        // mask index == q (1-channel planes)

        float4 O0, O1, O2;
        pixel(R.x, G.x, Bc.x, M.x, O0.x, O1.x, O2.x);
        pixel(R.y, G.y, Bc.y, M.y, O0.y, O1.y, O2.y);
        pixel(R.z, G.z, Bc.z, M.z, O0.z, O1.z, O2.z);
        pixel(R.w, G.w, Bc.w, M.w, O0.w, O1.w, O2.w);

        out4[base]              = O0;
        out4[base + PLANE4]     = O1;
        out4[base + 2 * PLANE4] = O2;
    }
}

extern "C" void kernel_launch(void* const* d_in, const int* in_sizes, int n_in,
                              void* d_out, int out_size)
{
    const float* img  = (const float*)d_in[0];
    const float* mask = (const float*)d_in[1];
    const float* qi_w = (const float*)d_in[2];
    const float* qi_b = (const float*)d_in[3];
    const float* ki_w = (const float*)d_in[4];
    const float* ki_b = (const float*)d_in[5];
    const float* vi_w = (const float*)d_in[6];
    const float* vi_b = (const float*)d_in[7];
    const float* qr_w = (const float*)d_in[8];
    const float* qr_b = (const float*)d_in[9];
    const float* kr_w = (const float*)d_in[10];
    const float* kr_b = (const float*)d_in[11];
    const float* vr_w = (const float*)d_in[12];
    const float* vr_b = (const float*)d_in[13];
    const float* fu_w = (const float*)d_in[14];
    const float* fu_b = (const float*)d_in[15];

    const int n_pix = in_sizes[1];      // B*H*W (mask element count)
    const int n_q   = n_pix / 4;        // float4 groups

    const int blocks = (n_q + THREADS * ITERS - 1) / (THREADS * ITERS);

    rim_kernel<<<blocks, THREADS>>>(img, mask,
                                    qi_w, qi_b, ki_w, ki_b, vi_w, vi_b,
                                    qr_w, qr_b, kr_w, kr_b, vr_w, vr_b,
                                    fu_w, fu_b,
                                    (float*)d_out, n_q);
}